// round 2
// baseline (speedup 1.0000x reference)
#include <cuda_runtime.h>
#include <cstdint>

#define BATCH 8
#define CIN 256
#define COUT 128
#define HIN 60
#define WIN 80
#define HUP 122
#define WUP 162
#define HOUT 120
#define WOUT 160
#define NPIX (HOUT*WOUT)   // 19200

// Scratch (static device globals — no runtime allocation)
__device__ float g_dw[(size_t)BATCH * CIN * NPIX];   // depthwise output, [b][c][h*160+w]
__device__ float g_pwT[CIN * COUT];                  // w_pw transposed, [c][o]

// ---------------------------------------------------------------------------
// Kernel 0: transpose pointwise weights [o][c] -> [c][o]
// ---------------------------------------------------------------------------
__global__ void tp_kernel(const float* __restrict__ pw) {
    int t = blockIdx.x * 256 + threadIdx.x;          // 0..32767
    if (t < CIN * COUT) {
        int c = t >> 7;
        int o = t & 127;
        g_pwT[t] = pw[o * CIN + c];
    }
}

// ---------------------------------------------------------------------------
// Kernel 1: bilinear upsample (align_corners=True) + 3x3 depthwise VALID conv
// One block per (b,c) plane. Vertical lerp staged in smem, horizontal lerp +
// depthwise done per 8-wide strip in registers.
// ---------------------------------------------------------------------------
__global__ __launch_bounds__(256) void dw_kernel(const float* __restrict__ x,
                                                 const float* __restrict__ wdw) {
    __shared__ float vs[HUP * WIN];                  // 122*80 = 39040 B

    int bc = blockIdx.x;                             // b*256 + c
    int c  = bc & (CIN - 1);
    const float* xp = x + (size_t)bc * (HIN * WIN);
    float* op = g_dw + (size_t)bc * NPIX;
    int tid = threadIdx.x;

    const float SY = (float)(59.0 / 121.0);          // (H-1)/(out_h-1), fp32 like JAX
    const float SX = (float)(79.0 / 161.0);

    // Vertical interpolation: vs[r][xc] for r in [0,122), xc in [0,80)
    for (int i = tid; i < HUP * WIN; i += 256) {
        int rr = i / WIN;
        int xc = i - rr * WIN;
        float hy  = rr * SY;
        float y0f = floorf(hy);
        int   y0  = (int)y0f;
        float fy  = hy - y0f;
        int   y1  = y0 + 1; if (y1 > HIN - 1) y1 = HIN - 1;
        float a  = xp[y0 * WIN + xc];
        float b2 = xp[y1 * WIN + xc];
        vs[i] = a + fy * (b2 - a);
    }

    float kd[9];
#pragma unroll
    for (int t = 0; t < 9; t++) kd[t] = __ldg(wdw + c * 9 + t);

    __syncthreads();

    // 2400 strips of 8 output pixels (20 strips per output row)
    for (int s = tid; s < 2400; s += 256) {
        int h  = s / 20;
        int w0 = (s - h * 20) * 8;

        float u[3][10];
#pragma unroll
        for (int j = 0; j < 10; j++) {
            int   cc  = w0 + j;
            float wx  = cc * SX;
            float x0f = floorf(wx);
            int   x0  = (int)x0f;
            float fx  = wx - x0f;
            int   x1  = x0 + 1; if (x1 > WIN - 1) x1 = WIN - 1;
#pragma unroll
            for (int i2 = 0; i2 < 3; i2++) {
                const float* vr = vs + (h + i2) * WIN;
                float a  = vr[x0];
                float b2 = vr[x1];
                u[i2][j] = a + fx * (b2 - a);
            }
        }

        float res[8];
#pragma unroll
        for (int ww = 0; ww < 8; ww++) {
            float acc = 0.0f;
#pragma unroll
            for (int i2 = 0; i2 < 3; i2++)
#pragma unroll
                for (int j = 0; j < 3; j++)
                    acc = fmaf(kd[i2 * 3 + j], u[i2][ww + j], acc);
            res[ww] = acc;
        }

        float4* dst = (float4*)(op + h * WOUT + w0);
        dst[0] = make_float4(res[0], res[1], res[2], res[3]);
        dst[1] = make_float4(res[4], res[5], res[6], res[7]);
    }
}

// ---------------------------------------------------------------------------
// Kernel 2: pointwise GEMM  out[b][o][p] = sum_c pwT[c][o] * dw[b][c][p]
// M=128, N=64 pixels per block, K=256 in chunks of 16.
// 256 threads: o_g = tid&31 owns 4 outs, px_g = tid>>5 owns 8 pixels.
// 16 f32x2 accumulators per thread (fma.rn.f32x2 = 2x fp32 rate on sm_103a).
// Register double-buffered smem staging (next chunk loaded during compute).
// ---------------------------------------------------------------------------
#define KC 16
#define TN 64

__global__ __launch_bounds__(256) void gemm_kernel(float* __restrict__ out) {
    __shared__ float dw_s[KC * TN];                  // 4 KB
    __shared__ float pw_s[KC * COUT];                // 8 KB

    int tid = threadIdx.x;
    int b   = blockIdx.x / 300;
    int p0  = (blockIdx.x - b * 300) * TN;

    const float* dwp = g_dw + (size_t)b * CIN * NPIX + p0;
    const float* pwp = g_pwT;

    int o_g  = tid & 31;                             // 4 output channels each
    int px_g = tid >> 5;                             // warp id -> 8 pixels
    int kld  = tid >> 4;                             // loader: k row 0..15
    int pxld = (tid & 15) << 2;                      // loader: pixel offset

    unsigned long long acc[4][4];
#pragma unroll
    for (int i = 0; i < 4; i++)
#pragma unroll
        for (int j = 0; j < 4; j++) acc[i][j] = 0ULL;

    // preload chunk 0 into registers
    float4 r_dw = *(const float4*)(dwp + (size_t)kld * NPIX + pxld);
    float4 r_p0 = *(const float4*)(pwp + tid * 8);
    float4 r_p1 = *(const float4*)(pwp + tid * 8 + 4);

    for (int ch = 0; ch < CIN / KC; ++ch) {
        __syncthreads();                             // prev compute done
        *(float4*)(dw_s + kld * TN + pxld) = r_dw;
        *(float4*)(pw_s + tid * 8)         = r_p0;
        *(float4*)(pw_s + tid * 8 + 4)     = r_p1;
        __syncthreads();

        if (ch + 1 < CIN / KC) {                     // prefetch next chunk
            int c0 = (ch + 1) * KC;
            r_dw = *(const float4*)(dwp + (size_t)(c0 + kld) * NPIX + pxld);
            r_p0 = *(const float4*)(pwp + c0 * COUT + tid * 8);
            r_p1 = *(const float4*)(pwp + c0 * COUT + tid * 8 + 4);
        }

#pragma unroll
        for (int k = 0; k < KC; ++k) {
            float4 pwv = *(const float4*)(pw_s + k * COUT + o_g * 4);
            // dw pairs: broadcast within warp (same px_g), loaded as b64 pairs
            ulonglong2 du0 = *(const ulonglong2*)(dw_s + k * TN + px_g * 8);
            ulonglong2 du1 = *(const ulonglong2*)(dw_s + k * TN + px_g * 8 + 4);
            unsigned long long d2[4] = {du0.x, du0.y, du1.x, du1.y};

            unsigned long long pw2[4];
            unsigned int pxi;
            pxi = __float_as_uint(pwv.x);
            asm("mov.b64 %0,{%1,%1};" : "=l"(pw2[0]) : "r"(pxi));
            pxi = __float_as_uint(pwv.y);
            asm("mov.b64 %0,{%1,%1};" : "=l"(pw2[1]) : "r"(pxi));
            pxi = __float_as_uint(pwv.z);
            asm("mov.b64 %0,{%1,%1};" : "=l"(pw2[2]) : "r"(pxi));
            pxi = __float_as_uint(pwv.w);
            asm("mov.b64 %0,{%1,%1};" : "=l"(pw2[3]) : "r"(pxi));

#pragma unroll
            for (int oi = 0; oi < 4; oi++)
#pragma unroll
                for (int pj = 0; pj < 4; pj++)
                    asm("fma.rn.f32x2 %0, %1, %2, %0;"
                        : "+l"(acc[oi][pj]) : "l"(pw2[oi]), "l"(d2[pj]));
        }
    }

    // epilogue: thread writes 4 outs x 8 contiguous pixels
    float* outp = out + (size_t)b * COUT * NPIX + p0 + px_g * 8;
#pragma unroll
    for (int oi = 0; oi < 4; oi++) {
        int o = o_g * 4 + oi;
        unsigned int l0, h0, l1, h1;
        asm("mov.b64 {%0,%1}, %2;" : "=r"(l0), "=r"(h0) : "l"(acc[oi][0]));
        asm("mov.b64 {%0,%1}, %2;" : "=r"(l1), "=r"(h1) : "l"(acc[oi][1]));
        float4 s0 = make_float4(__uint_as_float(l0), __uint_as_float(h0),
                                __uint_as_float(l1), __uint_as_float(h1));
        asm("mov.b64 {%0,%1}, %2;" : "=r"(l0), "=r"(h0) : "l"(acc[oi][2]));
        asm("mov.b64 {%0,%1}, %2;" : "=r"(l1), "=r"(h1) : "l"(acc[oi][3]));
        float4 s1 = make_float4(__uint_as_float(l0), __uint_as_float(h0),
                                __uint_as_float(l1), __uint_as_float(h1));
        *(float4*)(outp + (size_t)o * NPIX)     = s0;
        *(float4*)(outp + (size_t)o * NPIX + 4) = s1;
    }
}

// ---------------------------------------------------------------------------
// Launch
// ---------------------------------------------------------------------------
extern "C" void kernel_launch(void* const* d_in, const int* in_sizes, int n_in,
                              void* d_out, int out_size) {
    const float* x   = (const float*)d_in[0];   // [8,256,60,80]
    const float* wdw = (const float*)d_in[1];   // [256,1,3,3]
    const float* wpw = (const float*)d_in[2];   // [128,256]
    float* out = (float*)d_out;                 // [8,128,120,160]

    tp_kernel<<<128, 256>>>(wpw);
    dw_kernel<<<BATCH * CIN, 256>>>(x, wdw);
    gemm_kernel<<<BATCH * (NPIX / TN), 256>>>(out);
}

// round 6
// speedup vs baseline: 1.4777x; 1.4777x over previous
#include <cuda_runtime.h>
#include <cuda_bf16.h>
#include <cstdint>

#define BATCH 8
#define CIN 256
#define COUT 128
#define HIN 60
#define WIN 80
#define HUP 122
#define HOUT 120
#define WOUT 160
#define NPIX (HOUT*WOUT)   // 19200

// ---------------------------------------------------------------------------
// Device-global scratch
// ---------------------------------------------------------------------------
__device__ __align__(16) float         g_dw[(size_t)BATCH * CIN * NPIX]; // [b][c][p]
__device__ __align__(16) __nv_bfloat16 g_Ah[COUT * CIN];                 // pw hi [o][c]
__device__ __align__(16) __nv_bfloat16 g_Al[COUT * CIN];                 // pw lo [o][c]

// ---------------------------------------------------------------------------
// Kernel: split pointwise weights [o][c] fp32 -> bf16 hi/lo
// ---------------------------------------------------------------------------
__global__ void pwsplit_kernel(const float* __restrict__ pw) {
    int i = blockIdx.x * 256 + threadIdx.x;          // 0..32767
    float v = pw[i];
    __nv_bfloat16 h = __float2bfloat16(v);
    __nv_bfloat16 l = __float2bfloat16(v - __bfloat162float(h));
    g_Ah[i] = h;
    g_Al[i] = l;
}

// ---------------------------------------------------------------------------
// Kernel: bilinear upsample (align_corners) + 3x3 depthwise VALID
// (unchanged from the passing R1 kernel)
// ---------------------------------------------------------------------------
__global__ __launch_bounds__(256) void dw_kernel(const float* __restrict__ x,
                                                 const float* __restrict__ wdw) {
    __shared__ float vs[HUP * WIN];

    int bc = blockIdx.x;
    int c  = bc & (CIN - 1);
    const float* xp = x + (size_t)bc * (HIN * WIN);
    float* op = g_dw + (size_t)bc * NPIX;
    int tid = threadIdx.x;

    const float SY = (float)(59.0 / 121.0);
    const float SX = (float)(79.0 / 161.0);

    for (int i = tid; i < HUP * WIN; i += 256) {
        int rr = i / WIN;
        int xc = i - rr * WIN;
        float hy  = rr * SY;
        float y0f = floorf(hy);
        int   y0  = (int)y0f;
        float fy  = hy - y0f;
        int   y1  = y0 + 1; if (y1 > HIN - 1) y1 = HIN - 1;
        float a  = xp[y0 * WIN + xc];
        float b2 = xp[y1 * WIN + xc];
        vs[i] = a + fy * (b2 - a);
    }

    float kd[9];
#pragma unroll
    for (int t = 0; t < 9; t++) kd[t] = __ldg(wdw + c * 9 + t);

    __syncthreads();

    for (int s = tid; s < 2400; s += 256) {
        int h  = s / 20;
        int w0 = (s - h * 20) * 8;

        float u[3][10];
#pragma unroll
        for (int j = 0; j < 10; j++) {
            int   cc  = w0 + j;
            float wx  = cc * SX;
            float x0f = floorf(wx);
            int   x0  = (int)x0f;
            float fx  = wx - x0f;
            int   x1  = x0 + 1; if (x1 > WIN - 1) x1 = WIN - 1;
#pragma unroll
            for (int i2 = 0; i2 < 3; i2++) {
                const float* vr = vs + (h + i2) * WIN;
                float a  = vr[x0];
                float b2 = vr[x1];
                u[i2][j] = a + fx * (b2 - a);
            }
        }

        float res[8];
#pragma unroll
        for (int ww = 0; ww < 8; ww++) {
            float acc = 0.0f;
#pragma unroll
            for (int i2 = 0; i2 < 3; i2++)
#pragma unroll
                for (int j = 0; j < 3; j++)
                    acc = fmaf(kd[i2 * 3 + j], u[i2][ww + j], acc);
            res[ww] = acc;
        }

        float4* dst = (float4*)(op + h * WOUT + w0);
        dst[0] = make_float4(res[0], res[1], res[2], res[3]);
        dst[1] = make_float4(res[4], res[5], res[6], res[7]);
    }
}

// ---------------------------------------------------------------------------
// GEMM via mma.sync (HMMA) with split-bf16, 3 passes:
//   out[o][p] += Ah[o][k]*Bh[k][p] + Al*Bh + Ah*Bl   (fp32 accumulators)
// Block: 128(o) x 128(p), 8 warps, warp tile 64x32. K in chunks of 32.
// B converted from g_dw fp32 in-kernel (no transpose kernel needed).
// ---------------------------------------------------------------------------
#define APAD 40    // A smem row stride (elems): 32 + 8 pad -> conflict-free
#define BPAD 136   // B smem row stride (elems): 128 + 8 pad

__device__ __forceinline__ void mma_bf16(float* d, const uint32_t* a, const uint32_t* b) {
    asm volatile(
        "mma.sync.aligned.m16n8k16.row.col.f32.bf16.bf16.f32 "
        "{%0,%1,%2,%3}, {%4,%5,%6,%7}, {%8,%9}, {%0,%1,%2,%3};"
        : "+f"(d[0]), "+f"(d[1]), "+f"(d[2]), "+f"(d[3])
        : "r"(a[0]), "r"(a[1]), "r"(a[2]), "r"(a[3]), "r"(b[0]), "r"(b[1]));
}

__global__ __launch_bounds__(256) void gemm_kernel(float* __restrict__ out) {
    __shared__ __nv_bfloat16 Ash[128 * APAD];        // 10240 B
    __shared__ __nv_bfloat16 Als[128 * APAD];        // 10240 B
    __shared__ unsigned short Bhs[32 * BPAD];        //  8704 B
    __shared__ unsigned short Bls[32 * BPAD];        //  8704 B

    int tid  = threadIdx.x;
    int lane = tid & 31;
    int wid  = tid >> 5;

    int b  = blockIdx.x / (NPIX / 128);              // NPIX/128 = 150
    int p0 = (blockIdx.x - b * (NPIX / 128)) * 128;

    const float* dwp = g_dw + (size_t)b * CIN * NPIX + p0;

    int mw = (wid >> 2) * 64;                        // warp M offset
    int nw = (wid & 3) * 32;                         // warp N offset
    int g  = lane >> 2;                              // group id
    int q  = lane & 3;                               // thread-in-group

    float acc[4][4][4];
#pragma unroll
    for (int i = 0; i < 4; i++)
#pragma unroll
        for (int j = 0; j < 4; j++)
#pragma unroll
            for (int k = 0; k < 4; k++) acc[i][j][k] = 0.0f;

    for (int ck = 0; ck < CIN / 32; ++ck) {
        __syncthreads();                             // protect prev-iter reads

        // --- load A chunk [128 o][32 k] bf16 hi+lo (coalesced 16B) ---
#pragma unroll
        for (int i = 0; i < 2; i++) {
            int idx = tid + i * 256;                 // 0..511 uint4 segments
            int o = idx >> 2, qq = idx & 3;
            size_t goff = (size_t)o * 512 + (size_t)ck * 64 + qq * 16;
            uint4 vh = *(const uint4*)((const char*)g_Ah + goff);
            uint4 vl = *(const uint4*)((const char*)g_Al + goff);
            *(uint4*)((char*)Ash + o * (APAD * 2) + qq * 16) = vh;
            *(uint4*)((char*)Als + o * (APAD * 2) + qq * 16) = vl;
        }

        // --- load B chunk [32 c][128 p] fp32, convert to bf16 hi/lo ---
#pragma unroll
        for (int i = 0; i < 4; i++) {
            int idx = tid + i * 256;                 // 0..1023 float4 segments
            int c  = idx >> 5;
            int p4 = (idx & 31) * 4;
            float4 v = *(const float4*)(dwp + (size_t)(ck * 32 + c) * NPIX + p4);
            float vv[4] = {v.x, v.y, v.z, v.w};
            uint32_t h[4], l[4];
#pragma unroll
            for (int j = 0; j < 4; j++) {
                __nv_bfloat16 hh = __float2bfloat16(vv[j]);
                __nv_bfloat16 ll = __float2bfloat16(vv[j] - __bfloat162float(hh));
                h[j] = (uint32_t)__bfloat16_as_ushort(hh);
                l[j] = (uint32_t)__bfloat16_as_ushort(ll);
            }
            *(uint2*)&Bhs[c * BPAD + p4] =
                make_uint2(h[0] | (h[1] << 16), h[2] | (h[3] << 16));
            *(uint2*)&Bls[c * BPAD + p4] =
                make_uint2(l[0] | (l[1] << 16), l[2] | (l[3] << 16));
        }
        __syncthreads();

        // --- compute: 2 k16 steps per chunk ---
#pragma unroll
        for (int kk = 0; kk < 32; kk += 16) {
            int k0 = kk + q * 2;

            // B fragments (hi & lo), 4 n-tiles
            uint32_t bh[4][2], bl[4][2];
#pragma unroll
            for (int nt = 0; nt < 4; nt++) {
                int n = nw + nt * 8 + g;
                bh[nt][0] = (uint32_t)Bhs[k0 * BPAD + n] |
                            ((uint32_t)Bhs[(k0 + 1) * BPAD + n] << 16);
                bh[nt][1] = (uint32_t)Bhs[(k0 + 8) * BPAD + n] |
                            ((uint32_t)Bhs[(k0 + 9) * BPAD + n] << 16);
                bl[nt][0] = (uint32_t)Bls[k0 * BPAD + n] |
                            ((uint32_t)Bls[(k0 + 1) * BPAD + n] << 16);
                bl[nt][1] = (uint32_t)Bls[(k0 + 8) * BPAD + n] |
                            ((uint32_t)Bls[(k0 + 9) * BPAD + n] << 16);
            }

            // A-hi fragments, 4 m-tiles
            uint32_t ah[4][4];
#pragma unroll
            for (int mt = 0; mt < 4; mt++) {
                int m = mw + mt * 16 + g;
                ah[mt][0] = *(const uint32_t*)&Ash[m * APAD + k0];
                ah[mt][1] = *(const uint32_t*)&Ash[(m + 8) * APAD + k0];
                ah[mt][2] = *(const uint32_t*)&Ash[m * APAD + k0 + 8];
                ah[mt][3] = *(const uint32_t*)&Ash[(m + 8) * APAD + k0 + 8];
            }

            // pass 1: Ah * Bh
#pragma unroll
            for (int mt = 0; mt < 4; mt++)
#pragma unroll
                for (int nt = 0; nt < 4; nt++)
                    mma_bf16(acc[mt][nt], ah[mt], bh[nt]);

            // pass 2: Al * Bh
            uint32_t al[4][4];
#pragma unroll
            for (int mt = 0; mt < 4; mt++) {
                int m = mw + mt * 16 + g;
                al[mt][0] = *(const uint32_t*)&Als[m * APAD + k0];
                al[mt][1] = *(const uint32_t*)&Als[(m + 8) * APAD + k0];
                al[mt][2] = *(const uint32_t*)&Als[m * APAD + k0 + 8];
                al[mt][3] = *(const uint32_t*)&Als[(m + 8) * APAD + k0 + 8];
            }
#pragma unroll
            for (int mt = 0; mt < 4; mt++)
#pragma unroll
                for (int nt = 0; nt < 4; nt++)
                    mma_bf16(acc[mt][nt], al[mt], bh[nt]);

            // pass 3: Ah * Bl
#pragma unroll
            for (int mt = 0; mt < 4; mt++)
#pragma unroll
                for (int nt = 0; nt < 4; nt++)
                    mma_bf16(acc[mt][nt], ah[mt], bl[nt]);
        }
    }

    // --- epilogue ---
    float* base = out + (size_t)b * COUT * NPIX + p0;
#pragma unroll
    for (int mt = 0; mt < 4; mt++) {
#pragma unroll
        for (int nt = 0; nt < 4; nt++) {
            int m = mw + mt * 16 + g;
            int n = nw + nt * 8 + q * 2;
            *(float2*)&base[(size_t)m * NPIX + n] =
                make_float2(acc[mt][nt][0], acc[mt][nt][1]);
            *(float2*)&base[(size_t)(m + 8) * NPIX + n] =
                make_float2(acc[mt][nt][2], acc[mt][nt][3]);
        }
    }
}

// ---------------------------------------------------------------------------
// Launch
// ---------------------------------------------------------------------------
extern "C" void kernel_launch(void* const* d_in, const int* in_sizes, int n_in,
                              void* d_out, int out_size) {
    const float* x   = (const float*)d_in[0];   // [8,256,60,80]
    const float* wdw = (const float*)d_in[1];   // [256,1,3,3]
    const float* wpw = (const float*)d_in[2];   // [128,256]
    float* out = (float*)d_out;                 // [8,128,120,160]

    pwsplit_kernel<<<128, 256>>>(wpw);
    dw_kernel<<<BATCH * CIN, 256>>>(x, wdw);
    gemm_kernel<<<BATCH * (NPIX / 128), 256>>>(out);
}